// round 1
// baseline (speedup 1.0000x reference)
#include <cuda_runtime.h>
#include <math.h>

// CapsuleLayer: u_hat[b,c,r,o] = sum_i W[c,r,o,i] * x[b,r,i]; out = squash(u_hat) over o.
// B=256, C=10, R=1152, O=16, I=8.
//
// Block = (r, c). 256 threads = 256 b values. W[c,r] (128 floats) staged in smem,
// read via broadcast. Each thread computes all 16 outputs + squash locally.

#define NUM_CAPSULES 10
#define NUM_ROUTES   1152
#define IN_CH        8
#define OUT_CH       16

__global__ __launch_bounds__(256) void capsule_kernel(
    const float* __restrict__ x,   // [B, R, 8]
    const float* __restrict__ W,   // [C, R, 16, 8]
    float* __restrict__ out,       // [B, C, R, 16]
    int B)
{
    __shared__ float4 Ws[32];      // 128 floats = W[c, r, :, :]

    const int r = blockIdx.x;
    const int c = blockIdx.y;

    // Stage W tile: 32 float4 loads by first 32 threads.
    const float4* Wg = reinterpret_cast<const float4*>(
        W + ((size_t)c * NUM_ROUTES + r) * (OUT_CH * IN_CH));
    if (threadIdx.x < 32) {
        Ws[threadIdx.x] = Wg[threadIdx.x];
    }
    __syncthreads();

    const int b = threadIdx.x;
    if (b >= B) return;

    // Load x[b, r, 0..7] — 32 bytes, sector aligned.
    const float4* xg = reinterpret_cast<const float4*>(
        x + ((size_t)b * NUM_ROUTES + r) * IN_CH);
    const float4 x0 = xg[0];
    const float4 x1 = xg[1];

    const float* Wf = reinterpret_cast<const float*>(Ws);

    float u[OUT_CH];
    float sq = 0.0f;
#pragma unroll
    for (int o = 0; o < OUT_CH; o++) {
        const float* w = Wf + o * IN_CH;
        float acc = w[0] * x0.x;
        acc = fmaf(w[1], x0.y, acc);
        acc = fmaf(w[2], x0.z, acc);
        acc = fmaf(w[3], x0.w, acc);
        acc = fmaf(w[4], x1.x, acc);
        acc = fmaf(w[5], x1.y, acc);
        acc = fmaf(w[6], x1.z, acc);
        acc = fmaf(w[7], x1.w, acc);
        u[o] = acc;
        sq = fmaf(acc, acc, sq);
    }

    // squash: scale = sq/(1+sq)/sqrt(sq+1e-9)
    const float inv_norm = rsqrtf(sq + 1e-9f);
    const float scale = sq * inv_norm / (1.0f + sq);

    float4* og = reinterpret_cast<float4*>(
        out + (((size_t)b * NUM_CAPSULES + c) * NUM_ROUTES + r) * OUT_CH);
#pragma unroll
    for (int o4 = 0; o4 < 4; o4++) {
        og[o4] = make_float4(u[o4 * 4 + 0] * scale,
                             u[o4 * 4 + 1] * scale,
                             u[o4 * 4 + 2] * scale,
                             u[o4 * 4 + 3] * scale);
    }
}

extern "C" void kernel_launch(void* const* d_in, const int* in_sizes, int n_in,
                              void* d_out, int out_size)
{
    const float* x = (const float*)d_in[0];   // [B, 1152, 8]
    const float* W = (const float*)d_in[1];   // [1, 10, 1152, 16, 8]
    float* out = (float*)d_out;               // [B, 10, 1152, 16]

    const int B = in_sizes[0] / (NUM_ROUTES * IN_CH);   // 256

    dim3 grid(NUM_ROUTES, NUM_CAPSULES);
    dim3 block(B);
    capsule_kernel<<<grid, block>>>(x, W, out, B);
}

// round 4
// speedup vs baseline: 1.6531x; 1.6531x over previous
#include <cuda_runtime.h>
#include <math.h>

// CapsuleLayer: u_hat[b,c,r,o] = sum_i W[c,r,o,i]*x[b,r,i]; out = squash over o.
// B=256, C=10, R=1152, O=16, I=8.
//
// Decomposition (coalescing-first):
//   grid = (R/64, C * BCHUNKS) 2D; 256 threads.
//   thread t <-> (rr = t/4, op = t%4): route r0+rr, outputs o = 4*op..4*op+3.
//   W[c,r,4op:4op+4,0:8] = 32 contiguous floats -> registers, loaded once per block.
//   Loop over 64 b values (unroll 2): x row broadcast among 4 lanes (warp reads
//   256B contiguous), 16-wide dot x4, sum-of-squares via 2x shfl.bfly over the
//   4-lane o-group, STG.128 fully coalesced (warp writes 512B contiguous).

#define NUM_CAPSULES 10
#define NUM_ROUTES   1152
#define IN_CH        8
#define OUT_CH       16
#define RT           64     // routes per block
#define BCHUNKS      4
#define BCHUNK_LEN   64     // 256 / BCHUNKS

__device__ __forceinline__ float dot8(const float4 wa, const float4 wb,
                                      const float4 x0, const float4 x1)
{
    float acc = wa.x * x0.x;
    acc = fmaf(wa.y, x0.y, acc);
    acc = fmaf(wa.z, x0.z, acc);
    acc = fmaf(wa.w, x0.w, acc);
    acc = fmaf(wb.x, x1.x, acc);
    acc = fmaf(wb.y, x1.y, acc);
    acc = fmaf(wb.z, x1.z, acc);
    acc = fmaf(wb.w, x1.w, acc);
    return acc;
}

__global__ __launch_bounds__(256) void capsule_kernel(
    const float* __restrict__ x,   // [B, R, 8]
    const float* __restrict__ W,   // [C, R, 16, 8]
    float* __restrict__ out)       // [B, C, R, 16]
{
    const int tid = threadIdx.x;
    const int rr  = tid >> 2;          // 0..63
    const int op  = tid & 3;           // 0..3  (o = 4*op .. 4*op+3)
    const int r   = blockIdx.x * RT + rr;
    const int c   = blockIdx.y / BCHUNKS;
    const int b0  = (blockIdx.y % BCHUNKS) * BCHUNK_LEN;

    // This thread's 32 W floats (4 outputs x 8 inputs, contiguous) -> registers.
    const float4* Wg = reinterpret_cast<const float4*>(
        W + (((size_t)c * NUM_ROUTES + r) * OUT_CH + op * 4) * IN_CH);
    float4 w[8];
#pragma unroll
    for (int j = 0; j < 8; j++) w[j] = Wg[j];

    const size_t x_row  = (size_t)r * IN_CH;
    const size_t o_base = ((size_t)c * NUM_ROUTES + r) * OUT_CH + op * 4;
    const size_t XB = (size_t)NUM_ROUTES * IN_CH;                     // x batch stride
    const size_t OB = (size_t)NUM_CAPSULES * NUM_ROUTES * OUT_CH;     // out batch stride

#pragma unroll 2
    for (int bb = 0; bb < BCHUNK_LEN; bb++) {
        const int b = b0 + bb;
        const float4* xg = reinterpret_cast<const float4*>(x + (size_t)b * XB + x_row);
        const float4 x0 = xg[0];
        const float4 x1 = xg[1];

        float u0 = dot8(w[0], w[1], x0, x1);
        float u1 = dot8(w[2], w[3], x0, x1);
        float u2 = dot8(w[4], w[5], x0, x1);
        float u3 = dot8(w[6], w[7], x0, x1);

        float sq = u0 * u0;
        sq = fmaf(u1, u1, sq);
        sq = fmaf(u2, u2, sq);
        sq = fmaf(u3, u3, sq);
        sq += __shfl_xor_sync(0xFFFFFFFFu, sq, 1);
        sq += __shfl_xor_sync(0xFFFFFFFFu, sq, 2);

        // squash scale = sq/(1+sq)/sqrt(sq+1e-9)
        const float inv   = rsqrtf(sq + 1e-9f);
        const float scale = __fdividef(sq * inv, 1.0f + sq);

        float4* og = reinterpret_cast<float4*>(out + (size_t)b * OB + o_base);
        og[0] = make_float4(u0 * scale, u1 * scale, u2 * scale, u3 * scale);
    }
}

extern "C" void kernel_launch(void* const* d_in, const int* in_sizes, int n_in,
                              void* d_out, int out_size)
{
    const float* x = (const float*)d_in[0];   // [B, 1152, 8]
    const float* W = (const float*)d_in[1];   // [1, 10, 1152, 16, 8]
    float* out = (float*)d_out;               // [B, 10, 1152, 16]

    dim3 grid(NUM_ROUTES / RT, NUM_CAPSULES * BCHUNKS);  // 18 x 40 = 720 blocks
    dim3 block(256);
    capsule_kernel<<<grid, block>>>(x, W, out);
}

// round 5
// speedup vs baseline: 1.8065x; 1.0927x over previous
#include <cuda_runtime.h>
#include <math.h>

// CapsuleLayer: u_hat[b,c,r,o] = sum_i W[c,r,o,i]*x[b,r,i]; out = squash over o.
// B=256, C=10, R=1152, O=16, I=8.
//
// Decomposition (coalescing-first):
//   grid = (R/64, C * BCHUNKS) 2D; 256 threads; 16 b-values per block.
//   thread t <-> (rr = t/4, op = t%4): route r0+rr, outputs o = 4*op..4*op+3.
//   W[c,r,4op:4op+4,0:8] = 32 contiguous floats -> registers, loaded once per block.
//   b-loop unrolled x4 with all 8 x-loads front-batched (MLP=8/thread); the four
//   independent shfl/rsqrt epilogue tails interleave. Warp reads 256B contiguous
//   per b (4-lane broadcast groups), warp writes 512B contiguous STG.128.

#define NUM_CAPSULES 10
#define NUM_ROUTES   1152
#define IN_CH        8
#define OUT_CH       16
#define RT           64     // routes per block
#define BCHUNKS      16
#define BCHUNK_LEN   16     // 256 / BCHUNKS
#define UNROLL       4

__device__ __forceinline__ float dot8(const float4 wa, const float4 wb,
                                      const float4 x0, const float4 x1)
{
    float acc = wa.x * x0.x;
    acc = fmaf(wa.y, x0.y, acc);
    acc = fmaf(wa.z, x0.z, acc);
    acc = fmaf(wa.w, x0.w, acc);
    acc = fmaf(wb.x, x1.x, acc);
    acc = fmaf(wb.y, x1.y, acc);
    acc = fmaf(wb.z, x1.z, acc);
    acc = fmaf(wb.w, x1.w, acc);
    return acc;
}

__global__ __launch_bounds__(256) void capsule_kernel(
    const float* __restrict__ x,   // [B, R, 8]
    const float* __restrict__ W,   // [C, R, 16, 8]
    float* __restrict__ out)       // [B, C, R, 16]
{
    const int tid = threadIdx.x;
    const int rr  = tid >> 2;          // 0..63
    const int op  = tid & 3;           // 0..3  (o = 4*op .. 4*op+3)
    const int r   = blockIdx.x * RT + rr;
    const int c   = blockIdx.y / BCHUNKS;
    const int b0  = (blockIdx.y % BCHUNKS) * BCHUNK_LEN;

    // This thread's 32 W floats (4 outputs x 8 inputs, contiguous) -> registers.
    const float4* Wg = reinterpret_cast<const float4*>(
        W + (((size_t)c * NUM_ROUTES + r) * OUT_CH + op * 4) * IN_CH);
    float4 w[8];
#pragma unroll
    for (int j = 0; j < 8; j++) w[j] = Wg[j];

    const size_t x_row  = (size_t)r * IN_CH;
    const size_t o_base = ((size_t)c * NUM_ROUTES + r) * OUT_CH + op * 4;
    const size_t XB = (size_t)NUM_ROUTES * IN_CH;                     // x batch stride
    const size_t OB = (size_t)NUM_CAPSULES * NUM_ROUTES * OUT_CH;     // out batch stride

#pragma unroll 1
    for (int bb = 0; bb < BCHUNK_LEN; bb += UNROLL) {
        // Front-batch all UNROLL x-row loads (8 LDG.128 in flight).
        float4 xv[UNROLL][2];
#pragma unroll
        for (int k = 0; k < UNROLL; k++) {
            const float4* xg = reinterpret_cast<const float4*>(
                x + (size_t)(b0 + bb + k) * XB + x_row);
            xv[k][0] = xg[0];
            xv[k][1] = xg[1];
        }

#pragma unroll
        for (int k = 0; k < UNROLL; k++) {
            const int b = b0 + bb + k;
            const float4 x0 = xv[k][0];
            const float4 x1 = xv[k][1];

            float u0 = dot8(w[0], w[1], x0, x1);
            float u1 = dot8(w[2], w[3], x0, x1);
            float u2 = dot8(w[4], w[5], x0, x1);
            float u3 = dot8(w[6], w[7], x0, x1);

            float sq = u0 * u0;
            sq = fmaf(u1, u1, sq);
            sq = fmaf(u2, u2, sq);
            sq = fmaf(u3, u3, sq);
            sq += __shfl_xor_sync(0xFFFFFFFFu, sq, 1);
            sq += __shfl_xor_sync(0xFFFFFFFFu, sq, 2);

            // squash scale = sq/(1+sq)/sqrt(sq+1e-9)
            const float inv   = rsqrtf(sq + 1e-9f);
            const float scale = __fdividef(sq * inv, 1.0f + sq);

            float4* og = reinterpret_cast<float4*>(out + (size_t)b * OB + o_base);
            og[0] = make_float4(u0 * scale, u1 * scale, u2 * scale, u3 * scale);
        }
    }
}

extern "C" void kernel_launch(void* const* d_in, const int* in_sizes, int n_in,
                              void* d_out, int out_size)
{
    const float* x = (const float*)d_in[0];   // [B, 1152, 8]
    const float* W = (const float*)d_in[1];   // [1, 10, 1152, 16, 8]
    float* out = (float*)d_out;               // [B, 10, 1152, 16]

    dim3 grid(NUM_ROUTES / RT, NUM_CAPSULES * BCHUNKS);  // 18 x 160 = 2880 blocks
    dim3 block(256);
    capsule_kernel<<<grid, block>>>(x, W, out);
}

// round 7
// speedup vs baseline: 1.9166x; 1.0610x over previous
#include <cuda_runtime.h>
#include <cstdint>
#include <math.h>

// CapsuleLayer: u_hat[b,c,r,o] = sum_i W[c,r,o,i]*x[b,r,i]; out = squash over o.
// B=256, C=10, R=1152, O=16, I=8.
//
// grid = (R/32, C*16); block = 128 threads; 16 b per block.
// thread t <-> (rr = t/4, op = t%4): route, o-quad. W in registers as f32x2 pairs.
// Dots via packed fma.rn.f32x2 (half the FMA instructions, shorter chains).
// squash with a single MUFU: scale = sq * rsqrt((sq+eps)*(1+sq)^2).
// Warp x-load 256B contiguous (4-lane broadcast), STG.128 warp-contiguous 512B.

#define NUM_CAPSULES 10
#define NUM_ROUTES   1152
#define IN_CH        8
#define OUT_CH       16
#define RT           32     // routes per block (128 threads / 4 lanes)
#define BCHUNKS      16
#define BCHUNK_LEN   16     // 256 / BCHUNKS
#define UNROLL       4

__device__ __forceinline__ uint64_t f2mul(uint64_t a, uint64_t b)
{
    uint64_t d;
    asm("mul.rn.f32x2 %0, %1, %2;" : "=l"(d) : "l"(a), "l"(b));
    return d;
}
__device__ __forceinline__ uint64_t f2fma(uint64_t a, uint64_t b, uint64_t c)
{
    uint64_t d;
    asm("fma.rn.f32x2 %0, %1, %2, %3;" : "=l"(d) : "l"(a), "l"(b), "l"(c));
    return d;
}
__device__ __forceinline__ float f2hsum(uint64_t v)
{
    float lo, hi;
    asm("mov.b64 {%0, %1}, %2;" : "=f"(lo), "=f"(hi) : "l"(v));
    return lo + hi;
}

__device__ __forceinline__ float dot8p(const ulonglong2 wa, const ulonglong2 wb,
                                       const ulonglong2 xa, const ulonglong2 xb)
{
    uint64_t t = f2mul(wa.x, xa.x);
    t = f2fma(wa.y, xa.y, t);
    t = f2fma(wb.x, xb.x, t);
    t = f2fma(wb.y, xb.y, t);
    return f2hsum(t);
}

__global__ __launch_bounds__(128) void capsule_kernel(
    const float* __restrict__ x,   // [B, R, 8]
    const float* __restrict__ W,   // [C, R, 16, 8]
    float* __restrict__ out)       // [B, C, R, 16]
{
    const int tid = threadIdx.x;
    const int rr  = tid >> 2;          // 0..31
    const int op  = tid & 3;           // 0..3  (o = 4*op .. 4*op+3)
    const int r   = blockIdx.x * RT + rr;
    const int c   = blockIdx.y / BCHUNKS;
    const int b0  = (blockIdx.y % BCHUNKS) * BCHUNK_LEN;

    // This thread's 32 W floats (4 outputs x 8 inputs) as 8 ulonglong2 (f32x2 pairs).
    const ulonglong2* Wg = reinterpret_cast<const ulonglong2*>(
        W + (((size_t)c * NUM_ROUTES + r) * OUT_CH + op * 4) * IN_CH);
    ulonglong2 w[8];
#pragma unroll
    for (int j = 0; j < 8; j++) w[j] = Wg[j];

    const size_t x_row  = (size_t)r * IN_CH;
    const size_t o_base = ((size_t)c * NUM_ROUTES + r) * OUT_CH + op * 4;
    const size_t XB = (size_t)NUM_ROUTES * IN_CH;                     // x batch stride
    const size_t OB = (size_t)NUM_CAPSULES * NUM_ROUTES * OUT_CH;     // out batch stride

#pragma unroll 1
    for (int bb = 0; bb < BCHUNK_LEN; bb += UNROLL) {
        // Front-batch all UNROLL x-row loads (8 LDG.128 in flight).
        ulonglong2 xv[UNROLL][2];
#pragma unroll
        for (int k = 0; k < UNROLL; k++) {
            const ulonglong2* xg = reinterpret_cast<const ulonglong2*>(
                x + (size_t)(b0 + bb + k) * XB + x_row);
            xv[k][0] = xg[0];
            xv[k][1] = xg[1];
        }

#pragma unroll
        for (int k = 0; k < UNROLL; k++) {
            const int b = b0 + bb + k;
            const ulonglong2 xa = xv[k][0];
            const ulonglong2 xb = xv[k][1];

            float u0 = dot8p(w[0], w[1], xa, xb);
            float u1 = dot8p(w[2], w[3], xa, xb);
            float u2 = dot8p(w[4], w[5], xa, xb);
            float u3 = dot8p(w[6], w[7], xa, xb);

            float sq = u0 * u0;
            sq = fmaf(u1, u1, sq);
            sq = fmaf(u2, u2, sq);
            sq = fmaf(u3, u3, sq);
            sq += __shfl_xor_sync(0xFFFFFFFFu, sq, 1);
            sq += __shfl_xor_sync(0xFFFFFFFFu, sq, 2);

            // squash: scale = sq/(1+sq)/sqrt(sq+1e-9) = sq*rsqrt((sq+1e-9)*(1+sq)^2)
            const float opl  = 1.0f + sq;
            const float scale = sq * rsqrtf((sq + 1e-9f) * (opl * opl));

            float4* og = reinterpret_cast<float4*>(out + (size_t)b * OB + o_base);
            og[0] = make_float4(u0 * scale, u1 * scale, u2 * scale, u3 * scale);
        }
    }
}

extern "C" void kernel_launch(void* const* d_in, const int* in_sizes, int n_in,
                              void* d_out, int out_size)
{
    const float* x = (const float*)d_in[0];   // [B, 1152, 8]
    const float* W = (const float*)d_in[1];   // [1, 10, 1152, 16, 8]
    float* out = (float*)d_out;               // [B, 10, 1152, 16]

    dim3 grid(NUM_ROUTES / RT, NUM_CAPSULES * BCHUNKS);  // 36 x 160 = 5760 blocks
    dim3 block(128);
    capsule_kernel<<<grid, block>>>(x, W, out);
}

// round 9
// speedup vs baseline: 2.1033x; 1.0974x over previous
#include <cuda_runtime.h>
#include <cstdint>
#include <math.h>

// CapsuleLayer: u_hat[b,c,r,o] = sum_i W[c,r,o,i]*x[b,r,i]; out = squash over o.
// B=256, C=10, R=1152, O=16, I=8.
//
// Block = (32 routes, 16 batches), loops over ALL 10 capsules:
//   - x tile (16 b x 32 r x 32B = 16KB) staged to smem ONCE -> all x reads are
//     LDS (29 cyc) instead of global (~300-600 cyc); global x traffic /10.
//   - Route stride in smem = 48B: bank start = 12*rr mod 32 -> the 8 broadcast
//     groups of each LDS.128 hit all 32 banks exactly once (conflict-free).
//   - W[c, r, o-quad] (32 regs) reloaded per capsule from L2.
//   - f32x2 packed dots, single-MUFU squash, warp-coalesced STG.128 (512B).
// Grid 36x16 = 576 blocks -> single wave on 148 SMs.

#define NUM_CAPSULES 10
#define NUM_ROUTES   1152
#define IN_CH        8
#define OUT_CH       16
#define RT           32     // routes per block
#define BCHUNKS      16
#define BCHUNK_LEN   16     // 256 / BCHUNKS
#define RSTRIDE_F    12     // floats per route row in smem (48B, bank-swizzle)

__device__ __forceinline__ uint64_t f2mul(uint64_t a, uint64_t b)
{
    uint64_t d;
    asm("mul.rn.f32x2 %0, %1, %2;" : "=l"(d) : "l"(a), "l"(b));
    return d;
}
__device__ __forceinline__ uint64_t f2fma(uint64_t a, uint64_t b, uint64_t c)
{
    uint64_t d;
    asm("fma.rn.f32x2 %0, %1, %2, %3;" : "=l"(d) : "l"(a), "l"(b), "l"(c));
    return d;
}
__device__ __forceinline__ float f2hsum(uint64_t v)
{
    float lo, hi;
    asm("mov.b64 {%0, %1}, %2;" : "=f"(lo), "=f"(hi) : "l"(v));
    return lo + hi;
}

__device__ __forceinline__ float dot8p(const ulonglong2 wa, const ulonglong2 wb,
                                       const ulonglong2 xa, const ulonglong2 xb)
{
    uint64_t t = f2mul(wa.x, xa.x);
    t = f2fma(wa.y, xa.y, t);
    t = f2fma(wb.x, xb.x, t);
    t = f2fma(wb.y, xb.y, t);
    return f2hsum(t);
}

__global__ __launch_bounds__(128) void capsule_kernel(
    const float* __restrict__ x,   // [B, R, 8]
    const float* __restrict__ W,   // [C, R, 16, 8]
    float* __restrict__ out)       // [B, C, R, 16]
{
    __shared__ float x_s[BCHUNK_LEN * RT * RSTRIDE_F];   // 24 KB

    const int tid = threadIdx.x;
    const int rr  = tid >> 2;          // 0..31
    const int op  = tid & 3;           // 0..3  (o = 4*op .. 4*op+3)
    const int r0  = blockIdx.x * RT;
    const int r   = r0 + rr;
    const int b0  = blockIdx.y * BCHUNK_LEN;

    const size_t XB = (size_t)NUM_ROUTES * IN_CH;                   // x batch stride
    const size_t OB = (size_t)NUM_CAPSULES * NUM_ROUTES * OUT_CH;   // out batch stride

    // ---- Stage x tile: 16 b x 32 r x 2 float4, fully coalesced global reads. ----
#pragma unroll
    for (int it = 0; it < (BCHUNK_LEN * RT * 2) / 128; it++) {
        const int idx = it * 128 + tid;          // 0..1023
        const int bb  = idx >> 6;                // /64
        const int rem = idx & 63;
        const int rs  = rem >> 1;                // route within tile
        const int j   = rem & 1;                 // float4 half
        const float4 v = *reinterpret_cast<const float4*>(
            x + (size_t)(b0 + bb) * XB + (size_t)(r0 + rs) * IN_CH + j * 4);
        *reinterpret_cast<float4*>(
            x_s + bb * (RT * RSTRIDE_F) + rs * RSTRIDE_F + j * 4) = v;
    }
    __syncthreads();

    const float* xrow = x_s + rr * RSTRIDE_F;    // this thread-group's route

    const size_t w_step = (size_t)NUM_ROUTES * OUT_CH * IN_CH;      // per-capsule W stride
    const float* Wp = W + (((size_t)r) * OUT_CH + op * 4) * IN_CH;  // c = 0
    const size_t o_base0 = ((size_t)r) * OUT_CH + op * 4;           // c = 0

#pragma unroll 1
    for (int c = 0; c < NUM_CAPSULES; c++) {
        // This capsule's 32 W floats -> registers (8 x 16B, contiguous, coalesced).
        const ulonglong2* Wg = reinterpret_cast<const ulonglong2*>(Wp + c * w_step);
        ulonglong2 w[8];
#pragma unroll
        for (int j = 0; j < 8; j++) w[j] = Wg[j];

        const size_t o_base = o_base0 + (size_t)c * (NUM_ROUTES * OUT_CH);

#pragma unroll 2
        for (int bb = 0; bb < BCHUNK_LEN; bb++) {
            const ulonglong2 xa = *reinterpret_cast<const ulonglong2*>(
                xrow + bb * (RT * RSTRIDE_F));
            const ulonglong2 xb = *reinterpret_cast<const ulonglong2*>(
                xrow + bb * (RT * RSTRIDE_F) + 4);

            float u0 = dot8p(w[0], w[1], xa, xb);
            float u1 = dot8p(w[2], w[3], xa, xb);
            float u2 = dot8p(w[4], w[5], xa, xb);
            float u3 = dot8p(w[6], w[7], xa, xb);

            float sq = u0 * u0;
            sq = fmaf(u1, u1, sq);
            sq = fmaf(u2, u2, sq);
            sq = fmaf(u3, u3, sq);
            sq += __shfl_xor_sync(0xFFFFFFFFu, sq, 1);
            sq += __shfl_xor_sync(0xFFFFFFFFu, sq, 2);

            // squash: scale = sq/(1+sq)/sqrt(sq+1e-9) = sq*rsqrt((sq+1e-9)*(1+sq)^2)
            const float opl   = 1.0f + sq;
            const float scale = sq * rsqrtf((sq + 1e-9f) * (opl * opl));

            float4* og = reinterpret_cast<float4*>(
                out + (size_t)(b0 + bb) * OB + o_base);
            og[0] = make_float4(u0 * scale, u1 * scale, u2 * scale, u3 * scale);
        }
    }
}

extern "C" void kernel_launch(void* const* d_in, const int* in_sizes, int n_in,
                              void* d_out, int out_size)
{
    const float* x = (const float*)d_in[0];   // [B, 1152, 8]
    const float* W = (const float*)d_in[1];   // [1, 10, 1152, 16, 8]
    float* out = (float*)d_out;               // [B, 10, 1152, 16]

    dim3 grid(NUM_ROUTES / RT, BCHUNKS);      // 36 x 16 = 576 blocks
    dim3 block(128);
    capsule_kernel<<<grid, block>>>(x, W, out);
}